// round 13
// baseline (speedup 1.0000x reference)
#include <cuda_runtime.h>

// y = (U kron I2) @ x, U[i,i+1] = sqrt(i+1)
// x: (2D, B) fp32, D=4096, B=4096.
// out[r] = sqrt(r/2 + 1) * x[r+2] (rowwise), last two rows zero.
//
// FINAL — measured-best configuration (R7: bench 43.488us, ncu 36.58us,
// DRAM 73.5% = 5.82 TB/s). Converged at the GB300 mixed rd+wr HBM stream
// ceiling: DRAM% invariant at 73.5-74.2% across all geometries, MLP depths,
// cache policies, and occupancies tested (R1-R7). Traffic (128 MiB read +
// 128 MiB write) is irreducible.
//
// Geometry: one block per row pair (rows 2i, 2i+1 share coef = sqrt(i+1)).
// 256 threads x 8 front-batched float4 = 32 KiB/block. Streaming (.cs)
// loads/stores — zero reuse.

static constexpr int D = 4096;
static constexpr int B4 = 4096 / 4;          // 1024 float4 per row
static constexpr int PAIR4 = 2 * B4;         // 2048 float4 per row pair
static constexpr int NPAIRS = D;             // 4096 blocks
static constexpr int LAST_PAIR = D - 1;      // pair i = D-1 is all zero

__global__ void __launch_bounds__(256) destroy_kernel(const float4* __restrict__ in,
                                                      float4* __restrict__ out) {
    const int pair = blockIdx.x;
    const int tid = threadIdx.x;
    float4* opair = out + (size_t)pair * PAIR4;

    if (pair < LAST_PAIR) {
        const float coef = sqrtf((float)(pair + 1));
        const float4* ipair = in + (size_t)(pair + 1) * PAIR4;  // rows shifted by 2

        float4 v[8];
#pragma unroll
        for (int k = 0; k < 8; k++) {
            v[k] = __ldcs(ipair + tid + k * 256);
            v[k].x *= coef; v[k].y *= coef; v[k].z *= coef; v[k].w *= coef;
        }

#pragma unroll
        for (int k = 0; k < 8; k++)
            __stcs(opair + tid + k * 256, v[k]);
    } else {
        const float4 z = make_float4(0.f, 0.f, 0.f, 0.f);
#pragma unroll
        for (int k = 0; k < 8; k++)
            __stcs(opair + tid + k * 256, z);
    }
}

extern "C" void kernel_launch(void* const* d_in, const int* in_sizes, int n_in,
                              void* d_out, int out_size) {
    const float4* in = (const float4*)d_in[0];
    float4* out = (float4*)d_out;
    destroy_kernel<<<NPAIRS, 256>>>(in, out);
}